// round 3
// baseline (speedup 1.0000x reference)
#include <cuda_runtime.h>
#include <cuda_bf16.h>

// AvgPool over last 4 dims of [2,16,32,32,32,32], kernel=stride=2, pad=0.
// Collapsed: N = 2*16 = 32 "rows" of a [32,32,32,32] tensor.
// Output: [N,16,16,16,16].
//
// Each thread produces one float2 of output (2 adjacent outputs along d4).
// It reads 8 float4s: for each corner (a,b,c) in {0,1}^3 of the pooling
// window over (d1,d2,d3), the 4 contiguous d4 inputs [4p .. 4p+3].
//   out[2p]   = sum of .x+.y over the 8 vectors, * 1/16
//   out[2p+1] = sum of .z+.w over the 8 vectors, * 1/16
//
// All loads are 16B-aligned and warp-contiguous in 128B segments; the
// kernel is a pure HBM stream (134 MB in + 8.4 MB out).

// Input strides in float4 units (D4 = 32 floats = 8 float4 per row)
static constexpr int S_N  = 262144;  // 32^4 / 4
static constexpr int S_D1 = 8192;    // 32^3 / 4
static constexpr int S_D2 = 256;     // 32^2 / 4
static constexpr int S_D3 = 8;       // 32   / 4

__global__ void __launch_bounds__(256)
avgpool4d_kernel(const float4* __restrict__ in, float2* __restrict__ out,
                 int n_pairs)
{
    int tid = blockIdx.x * blockDim.x + threadIdx.x;
    if (tid >= n_pairs) return;

    // tid -> (n, o1, o2, o3, p); p = output-pair index along d4 (0..7)
    int p  =  tid        & 7;
    int o3 = (tid >> 3)  & 15;
    int o2 = (tid >> 7)  & 15;
    int o1 = (tid >> 11) & 15;
    int n  =  tid >> 15;

    // Base float4 index of the window origin
    int base = n * S_N + (2 * o1) * S_D1 + (2 * o2) * S_D2 + (2 * o3) * S_D3 + p;

    // 8 independent loads, front-batched for MLP
    float4 v0 = in[base];
    float4 v1 = in[base + S_D3];
    float4 v2 = in[base + S_D2];
    float4 v3 = in[base + S_D2 + S_D3];
    float4 v4 = in[base + S_D1];
    float4 v5 = in[base + S_D1 + S_D3];
    float4 v6 = in[base + S_D1 + S_D2];
    float4 v7 = in[base + S_D1 + S_D2 + S_D3];

    float lo = (v0.x + v0.y) + (v1.x + v1.y)
             + (v2.x + v2.y) + (v3.x + v3.y)
             + (v4.x + v4.y) + (v5.x + v5.y)
             + (v6.x + v6.y) + (v7.x + v7.y);
    float hi = (v0.z + v0.w) + (v1.z + v1.w)
             + (v2.z + v2.w) + (v3.z + v3.w)
             + (v4.z + v4.w) + (v5.z + v5.w)
             + (v6.z + v6.w) + (v7.z + v7.w);

    const float scale = 1.0f / 16.0f;
    out[tid] = make_float2(lo * scale, hi * scale);
}

extern "C" void kernel_launch(void* const* d_in, const int* in_sizes, int n_in,
                              void* d_out, int out_size)
{
    (void)in_sizes; (void)n_in;
    const float4* in = (const float4*)d_in[0];
    float2* out = (float2*)d_out;

    int n_pairs = out_size / 2;               // one float2 per thread
    int threads = 256;
    int blocks  = (n_pairs + threads - 1) / threads;  // 4096 for the ref shape
    avgpool4d_kernel<<<blocks, threads>>>(in, out, n_pairs);
}

// round 4
// speedup vs baseline: 1.0816x; 1.0816x over previous
#include <cuda_runtime.h>
#include <cuda_bf16.h>

// AvgPool over last 4 dims of [2,16,32,32,32,32], kernel=stride=2, pad=0.
// Collapsed: N = 2*16 rows of a [32,32,32,32] tensor -> out [N,16,16,16,16].
//
// Each thread produces one float4 of output (4 adjacent outputs along d4),
// reading 2 adjacent float4s per window corner over (d1,d2,d3) in {0,1}^3:
// 16 independent streaming LDG.128s, one STG.128. Pure HBM stream:
// 134 MB read-once + 8.4 MB write-once -> __ldcs/__stcs evict-first hints.

// Input strides in float4 units (D4 = 32 floats = 8 float4 per row)
static constexpr int S_N  = 262144;  // 32^4 / 4
static constexpr int S_D1 = 8192;    // 32^3 / 4
static constexpr int S_D2 = 256;     // 32^2 / 4
static constexpr int S_D3 = 8;       // 32   / 4

// Pairwise-reduce one corner's two adjacent float4s (8 input floats along d4)
// into the 4-output accumulator.
__device__ __forceinline__ void acc_corner(float4& acc, const float4& c0, const float4& c1)
{
    acc.x += c0.x + c0.y;
    acc.y += c0.z + c0.w;
    acc.z += c1.x + c1.y;
    acc.w += c1.z + c1.w;
}

__global__ void __launch_bounds__(256)
avgpool4d_kernel(const float4* __restrict__ in, float4* __restrict__ out,
                 int n_quads)
{
    int tid = blockIdx.x * blockDim.x + threadIdx.x;
    if (tid >= n_quads) return;

    // tid -> (n, o1, o2, o3, q); q = output float4 index along d4 (0..3)
    int q  =  tid        & 3;
    int o3 = (tid >> 2)  & 15;
    int o2 = (tid >> 6)  & 15;
    int o1 = (tid >> 10) & 15;
    int n  =  tid >> 14;

    // Base float4 index of the window origin; each corner reads base+off and base+off+1
    int base = n * S_N + (2 * o1) * S_D1 + (2 * o2) * S_D2 + (2 * o3) * S_D3 + 2 * q;

    const float4* p = in + base;

    // 16 independent streaming loads, front-batched for MLP
    float4 a0 = __ldcs(p);
    float4 a1 = __ldcs(p + 1);
    float4 b0 = __ldcs(p + S_D3);
    float4 b1 = __ldcs(p + S_D3 + 1);
    float4 c0 = __ldcs(p + S_D2);
    float4 c1 = __ldcs(p + S_D2 + 1);
    float4 d0 = __ldcs(p + S_D2 + S_D3);
    float4 d1 = __ldcs(p + S_D2 + S_D3 + 1);
    float4 e0 = __ldcs(p + S_D1);
    float4 e1 = __ldcs(p + S_D1 + 1);
    float4 f0 = __ldcs(p + S_D1 + S_D3);
    float4 f1 = __ldcs(p + S_D1 + S_D3 + 1);
    float4 g0 = __ldcs(p + S_D1 + S_D2);
    float4 g1 = __ldcs(p + S_D1 + S_D2 + 1);
    float4 h0 = __ldcs(p + S_D1 + S_D2 + S_D3);
    float4 h1 = __ldcs(p + S_D1 + S_D2 + S_D3 + 1);

    float4 acc = make_float4(0.f, 0.f, 0.f, 0.f);
    acc_corner(acc, a0, a1);
    acc_corner(acc, b0, b1);
    acc_corner(acc, c0, c1);
    acc_corner(acc, d0, d1);
    acc_corner(acc, e0, e1);
    acc_corner(acc, f0, f1);
    acc_corner(acc, g0, g1);
    acc_corner(acc, h0, h1);

    const float s = 1.0f / 16.0f;
    acc.x *= s; acc.y *= s; acc.z *= s; acc.w *= s;

    __stcs(out + tid, acc);
}

extern "C" void kernel_launch(void* const* d_in, const int* in_sizes, int n_in,
                              void* d_out, int out_size)
{
    (void)in_sizes; (void)n_in;
    const float4* in = (const float4*)d_in[0];
    float4* out = (float4*)d_out;

    int n_quads = out_size / 4;               // one float4 per thread
    int threads = 256;
    int blocks  = (n_quads + threads - 1) / threads;  // 2048 for the ref shape
    avgpool4d_kernel<<<blocks, threads>>>(in, out, n_quads);
}